// round 7
// baseline (speedup 1.0000x reference)
#include <cuda_runtime.h>
#include <cuda_bf16.h>
#include <mma.h>
#include <cmath>

using namespace nvcuda;

#define LL     1024
#define EE     768
#define PPD    128
#define HH     16
#define HDIM   48
#define NDEPTH 8
#define MLPD   3072
#define NFREQ  256

// ---------------- device-global scratch (no allocations allowed) ----------------
__device__ __align__(16) float g_x[LL*EE];
__device__ __align__(16) float g_h[LL*EE];
__device__ __align__(16) float g_qkv[LL*3*EE];
__device__ __align__(16) float g_y[LL*EE];
__device__ __align__(16) float g_mlp[LL*MLPD];
__device__ __align__(16) __nv_bfloat16 g_bh[(size_t)HH*LL*LL];   // 32 MB, [h][l][m]
__device__ float g_cpre[EE];
__device__ float g_cs[EE];
__device__ float g_ada[NDEPTH*6*EE + 2*EE];
__device__ float g_Apw[HH*PPD];
__device__ float g_Spw[HH];
__device__ float g_Cpw[HH];

// ---------------- init ----------------
__global__ void k_copy(const float* __restrict__ z) {
    int i = blockIdx.x*1024 + threadIdx.x;
    g_x[i] = z[i];
}

__global__ void k_prep(const float* __restrict__ g, const float* __restrict__ beta,
                       const float* __restrict__ w) {
    const int p = threadIdx.x; // 128
    for (int h = 0; h < HH; h++)
        g_Apw[h*PPD + p] = g[p] * w[h*PPD + p];
    if (p < HH) {
        float s = 0.f, c = 0.f;
        for (int q = 0; q < PPD; q++) {
            s += g[q]    * w[p*PPD + q];
            c += beta[q] * w[p*PPD + q];
        }
        g_Spw[p] = s; g_Cpw[p] = c;
    }
}

// ---------------- bias LN + head projection: 512 MB read, one thread per row ----------------
__global__ void __launch_bounds__(256) k_bias(const float* __restrict__ bias) {
    __shared__ __align__(16) float sA[HH*PPD];
    __shared__ float sSh[HH], sCh[HH];
    const int tid = threadIdx.x;
    for (int i = tid; i < HH*PPD; i += 256) sA[i] = g_Apw[i];
    if (tid < HH) { sSh[tid] = g_Spw[tid]; sCh[tid] = g_Cpw[tid]; }
    __syncthreads();
    const int row = blockIdx.x*256 + tid;      // row = l*1024 + m
    const float* xr = bias + (size_t)row*PPD;
    float acc[HH];
#pragma unroll
    for (int h = 0; h < HH; h++) acc[h] = 0.f;
    float s = 0.f, ss = 0.f;
#pragma unroll
    for (int ch = 0; ch < 4; ch++) {
        float4 xv[8];
#pragma unroll
        for (int j = 0; j < 8; j++) xv[j] = *(const float4*)&xr[ch*32 + j*4];
#pragma unroll
        for (int j = 0; j < 8; j++) {
            s  += xv[j].x + xv[j].y + xv[j].z + xv[j].w;
            ss += xv[j].x*xv[j].x + xv[j].y*xv[j].y + xv[j].z*xv[j].z + xv[j].w*xv[j].w;
        }
#pragma unroll
        for (int h = 0; h < HH; h++) {
            const float* ar = &sA[h*PPD + ch*32];
            float a0 = 0.f;
#pragma unroll
            for (int j = 0; j < 8; j++) {
                float4 av = *(const float4*)&ar[j*4];
                a0 += xv[j].x*av.x + xv[j].y*av.y + xv[j].z*av.z + xv[j].w*av.w;
            }
            acc[h] += a0;
        }
    }
    const float mu   = s * (1.0f/PPD);
    const float rstd = rsqrtf(ss*(1.0f/PPD) - mu*mu + 1e-6f);
    const int l = row >> 10, m = row & 1023;
#pragma unroll
    for (int h = 0; h < HH; h++) {
        float v = rstd*(acc[h] - mu*sSh[h]) + sCh[h];
        g_bh[((size_t)h << 20) + ((size_t)l << 10) + m] = __float2bfloat16(v);
    }
}

// ---------------- time embedding chain ----------------
__global__ void k_time1(const float* __restrict__ t, const float* __restrict__ t0_w,
                        const float* __restrict__ t0_b) {
    __shared__ float emb[NFREQ];
    const int tid = threadIdx.x; // 256
    if (tid < 128) {
        float f   = expf(-9.210340371976184f * (float)tid / 128.0f);
        float arg = t[0] * f;
        emb[tid]       = cosf(arg);
        emb[tid + 128] = sinf(arg);
    }
    __syncthreads();
    for (int j = tid; j < EE; j += 256) {
        float a = t0_b[j];
        const float* w = t0_w + (size_t)j*NFREQ;
        for (int i = 0; i < NFREQ; i++) a += emb[i]*w[i];
        g_cpre[j] = a / (1.f + expf(-a));
    }
}

__global__ void k_time2(const float* __restrict__ t2_w, const float* __restrict__ t2_b) {
    __shared__ float cp[EE];
    const int tid = threadIdx.x; // 256
    for (int i = tid; i < EE; i += 256) cp[i] = g_cpre[i];
    __syncthreads();
    for (int j = tid; j < EE; j += 256) {
        float a = t2_b[j];
        const float* w = t2_w + (size_t)j*EE;
        for (int i = 0; i < EE; i++) a += cp[i]*w[i];
        g_cs[j] = a / (1.f + expf(-a));
    }
}

// all adaLN vectors (8*4608 + 1536 rows), one warp per row
__global__ void k_ada(const float* __restrict__ aw, const float* __restrict__ ab,
                      const float* __restrict__ fw, const float* __restrict__ fb) {
    const int gw   = (blockIdx.x*blockDim.x + threadIdx.x) >> 5;
    const int lane = threadIdx.x & 31;
    const int total = NDEPTH*6*EE + 2*EE;
    if (gw >= total) return;
    const float* wrow; float b;
    if (gw < NDEPTH*6*EE) { wrow = aw + (size_t)gw*EE; b = ab[gw]; }
    else { int r = gw - NDEPTH*6*EE; wrow = fw + (size_t)r*EE; b = fb[r]; }
    float acc = 0.f;
    for (int i = lane; i < EE; i += 32) acc += g_cs[i]*wrow[i];
#pragma unroll
    for (int o = 16; o > 0; o >>= 1) acc += __shfl_xor_sync(0xffffffffu, acc, o);
    if (lane == 0) g_ada[gw] = acc + b;
}

// ---------------- LayerNorm + adaLN modulation ----------------
__global__ void __launch_bounds__(256) k_lnmod(const float* __restrict__ x,
                                               int sh_off, int sc_off,
                                               float* __restrict__ out) {
    const int row = blockIdx.x, tid = threadIdx.x;
    const float* xr = x + (size_t)row*EE;
    float v0 = xr[tid], v1 = xr[tid+256], v2 = xr[tid+512];
    float s  = v0 + v1 + v2;
    float ss = v0*v0 + v1*v1 + v2*v2;
    __shared__ float rs[8], rss[8];
#pragma unroll
    for (int o = 16; o > 0; o >>= 1) {
        s  += __shfl_xor_sync(0xffffffffu, s,  o);
        ss += __shfl_xor_sync(0xffffffffu, ss, o);
    }
    if ((tid & 31) == 0) { rs[tid>>5] = s; rss[tid>>5] = ss; }
    __syncthreads();
    float st = 0.f, sst = 0.f;
#pragma unroll
    for (int i = 0; i < 8; i++) { st += rs[i]; sst += rss[i]; }
    const float mu   = st * (1.0f/EE);
    const float rstd = rsqrtf(sst*(1.0f/EE) - mu*mu + 1e-6f);
    const float* sh = g_ada + sh_off;
    const float* sc = g_ada + sc_off;
    float* orow = out + (size_t)row*EE;
    orow[tid]     = (v0-mu)*rstd*(1.f+sc[tid])     + sh[tid];
    orow[tid+256] = (v1-mu)*rstd*(1.f+sc[tid+256]) + sh[tid+256];
    orow[tid+512] = (v2-mu)*rstd*(1.f+sc[tid+512]) + sh[tid+512];
}

// ---------------- tf32 wmma GEMM: C(MxN) = A(MxK) @ W(NxK)^T, fused epilogue ----------------
// EPI 0: out = acc+bias    EPI 1: out += g_ada[g_off+n]*(acc+bias)    EPI 2: out = gelu_tanh(acc+bias)
#define GBM 128
#define GBN 64
#define GBK 32
#define GLD 36

template<int EPI>
__global__ void __launch_bounds__(256) k_gemm(const float* __restrict__ A,
                                              const float* __restrict__ W,
                                              const float* __restrict__ bias,
                                              int g_off,
                                              float* __restrict__ out,
                                              int M, int N, int K) {
    __shared__ __align__(16) float smem[9216];   // sA 128x36 + sB 64x36; epilogue reuses as 8x(32x36)
    float* sA = smem;
    float* sB = smem + GBM*GLD;
    const int tid = threadIdx.x;
    const int warp = tid >> 5, lane = tid & 31;
    const int wm = warp & 3, wn = warp >> 2;
    const int m0 = blockIdx.y * GBM;
    const int n0 = blockIdx.x * GBN;

    wmma::fragment<wmma::accumulator,16,16,8,float> cf[2][2];
#pragma unroll
    for (int i = 0; i < 2; i++)
#pragma unroll
        for (int j = 0; j < 2; j++) wmma::fill_fragment(cf[i][j], 0.0f);

    for (int k0 = 0; k0 < K; k0 += GBK) {
#pragma unroll
        for (int i = 0; i < 16; i++) {
            int e = tid + i*256;
            sA[(e>>5)*GLD + (e&31)] = A[(size_t)(m0 + (e>>5))*K + k0 + (e&31)];
        }
#pragma unroll
        for (int i = 0; i < 8; i++) {
            int e = tid + i*256;
            sB[(e>>5)*GLD + (e&31)] = W[(size_t)(n0 + (e>>5))*K + k0 + (e&31)];
        }
        __syncthreads();
#pragma unroll
        for (int kk = 0; kk < 4; kk++) {
            wmma::fragment<wmma::matrix_a,16,16,8,wmma::precision::tf32,wmma::row_major> af[2];
            wmma::fragment<wmma::matrix_b,16,16,8,wmma::precision::tf32,wmma::col_major> bf[2];
#pragma unroll
            for (int i = 0; i < 2; i++) {
                wmma::load_matrix_sync(af[i], sA + (wm*32 + i*16)*GLD + kk*8, GLD);
#pragma unroll
                for (int q = 0; q < af[i].num_elements; q++) af[i].x[q] = wmma::__float_to_tf32(af[i].x[q]);
            }
#pragma unroll
            for (int j = 0; j < 2; j++) {
                wmma::load_matrix_sync(bf[j], sB + (wn*32 + j*16)*GLD + kk*8, GLD);
#pragma unroll
                for (int q = 0; q < bf[j].num_elements; q++) bf[j].x[q] = wmma::__float_to_tf32(bf[j].x[q]);
            }
#pragma unroll
            for (int i = 0; i < 2; i++)
#pragma unroll
                for (int j = 0; j < 2; j++) wmma::mma_sync(cf[i][j], af[i], bf[j], cf[i][j]);
        }
        __syncthreads();
    }
    float* cbuf = smem + warp*(32*GLD);
#pragma unroll
    for (int i = 0; i < 2; i++)
#pragma unroll
        for (int j = 0; j < 2; j++)
            wmma::store_matrix_sync(cbuf + (i*16)*GLD + j*16, cf[i][j], GLD, wmma::mem_row_major);
    __syncwarp();
    const int ncol = n0 + wn*32 + lane;
    const float bv = bias ? bias[ncol] : 0.0f;
    const float gv = (EPI == 1) ? g_ada[g_off + ncol] : 0.0f;
#pragma unroll 8
    for (int r = 0; r < 32; r++) {
        float v = cbuf[r*GLD + lane] + bv;
        size_t oi = (size_t)(m0 + wm*32 + r)*N + ncol;
        if (EPI == 0) {
            out[oi] = v;
        } else if (EPI == 1) {
            out[oi] = out[oi] + gv * v;
        } else {
            float tn = tanhf(0.7978845608028654f*(v + 0.044715f*v*v*v));
            out[oi] = 0.5f*v*(1.0f + tn);
        }
    }
}

// ---------------- fused flash attention: one CTA per (q-tile 64, head) ----------------
#define FLD  48
#define FLDS 36

__global__ void __launch_bounds__(128) k_flash() {
    __shared__ __align__(16) float fs[11648];
    float* sQ = fs;                // 64 x 48
    float* sK = fs + 3072;         // 32 x 48
    float* sV = fs + 4608;         // 32 x 48
    float* sO = fs + 6144;         // 64 x 48
    float* sS = fs + 9216;         // 64 x 36 (32 cols used)
    float* sM = fs + 11520;        // 64
    float* sL = fs + 11584;        // 64

    const int tid  = threadIdx.x;  // 128
    const int warp = tid >> 5;
    const int qt = blockIdx.x, hh = blockIdx.y;
    const int l0 = qt*64;
    const float scale = 0.14433756729740643f;   // 48^-0.5
    const int rr = tid >> 1, hf = tid & 1;

    // load scaled Q tile (64 x 48)
#pragma unroll
    for (int i = 0; i < 6; i++) {
        int e = tid + i*128;
        int r = e/12, c4 = e%12;
        float4 v = *(const float4*)&g_qkv[(size_t)(l0+r)*(3*EE) + hh*144 + c4*4];
        v.x *= scale; v.y *= scale; v.z *= scale; v.w *= scale;
        *(float4*)&sQ[r*FLD + c4*4] = v;
    }
    for (int i = tid; i < 64*FLD; i += 128) sO[i] = 0.0f;
    if (tid < 64) { sM[tid] = -1e30f; sL[tid] = 0.0f; }

    for (int mt = 0; mt < 32; mt++) {
        const int m0 = mt*32;
        __syncthreads();                       // protects sK/sV reuse (+ init on iter 0)
#pragma unroll
        for (int i = 0; i < 3; i++) {
            int e = tid + i*128;
            int r = e/12, c4 = e%12;
            *(float4*)&sK[r*FLD + c4*4] =
                *(const float4*)&g_qkv[(size_t)(m0+r)*(3*EE) + hh*144 + 48 + c4*4];
            *(float4*)&sV[r*FLD + c4*4] =
                *(const float4*)&g_qkv[(size_t)(m0+r)*(3*EE) + hh*144 + 96 + c4*4];
        }
        __syncthreads();
        // S = Q @ K^T : warp handles rows warp*16..+15, cols 0..31
#pragma unroll
        for (int nt = 0; nt < 2; nt++) {
            wmma::fragment<wmma::accumulator,16,16,8,float> sc;
            wmma::fill_fragment(sc, 0.0f);
#pragma unroll
            for (int k = 0; k < 6; k++) {
                wmma::fragment<wmma::matrix_a,16,16,8,wmma::precision::tf32,wmma::row_major> af;
                wmma::fragment<wmma::matrix_b,16,16,8,wmma::precision::tf32,wmma::col_major> bf;
                wmma::load_matrix_sync(af, sQ + warp*16*FLD + k*8, FLD);
                wmma::load_matrix_sync(bf, sK + nt*16*FLD + k*8, FLD);
#pragma unroll
                for (int q = 0; q < af.num_elements; q++) af.x[q] = wmma::__float_to_tf32(af.x[q]);
#pragma unroll
                for (int q = 0; q < bf.num_elements; q++) bf.x[q] = wmma::__float_to_tf32(bf.x[q]);
                wmma::mma_sync(sc, af, bf, sc);
            }
            wmma::store_matrix_sync(sS + warp*16*FLDS + nt*16, sc, FLDS, wmma::mem_row_major);
        }
        __syncthreads();
        // bias add + online softmax: 2 threads per row, 16 cols each
        {
            const int c0 = hf*16;
            const __nv_bfloat16* bp = &g_bh[((size_t)hh << 20) + ((size_t)(l0+rr) << 10) + m0 + c0];
            float* srow = sS + rr*FLDS + c0;
            float v[16];
            float mloc = -1e30f;
#pragma unroll
            for (int c = 0; c < 16; c++) {
                v[c] = srow[c] + __bfloat162float(bp[c]);
                mloc = fmaxf(mloc, v[c]);
            }
            mloc = fmaxf(mloc, __shfl_xor_sync(0xffffffffu, mloc, 1));
            float mprev = sM[rr];
            float mnew  = fmaxf(mprev, mloc);
            float sum = 0.f;
#pragma unroll
            for (int c = 0; c < 16; c++) {
                float p = __expf(v[c] - mnew);
                srow[c] = p;
                sum += p;
            }
            sum += __shfl_xor_sync(0xffffffffu, sum, 1);
            float factor = __expf(mprev - mnew);
            if (hf == 0) { sM[rr] = mnew; sL[rr] = sL[rr]*factor + sum; }
            float* orow = sO + rr*FLD + hf*24;
#pragma unroll
            for (int c = 0; c < 24; c++) orow[c] *= factor;
        }
        __syncthreads();
        // O += P(64x32) @ V(32x48) : warp handles its 16 rows, 3 col tiles
        {
            wmma::fragment<wmma::matrix_a,16,16,8,wmma::precision::tf32,wmma::row_major> pa[4];
#pragma unroll
            for (int kk = 0; kk < 4; kk++) {
                wmma::load_matrix_sync(pa[kk], sS + warp*16*FLDS + kk*8, FLDS);
#pragma unroll
                for (int q = 0; q < pa[kk].num_elements; q++) pa[kk].x[q] = wmma::__float_to_tf32(pa[kk].x[q]);
            }
#pragma unroll
            for (int j = 0; j < 3; j++) {
                wmma::fragment<wmma::accumulator,16,16,8,float> of;
                wmma::load_matrix_sync(of, sO + warp*16*FLD + j*16, FLD, wmma::mem_row_major);
#pragma unroll
                for (int kk = 0; kk < 4; kk++) {
                    wmma::fragment<wmma::matrix_b,16,16,8,wmma::precision::tf32,wmma::row_major> vb;
                    wmma::load_matrix_sync(vb, sV + kk*8*FLD + j*16, FLD);
#pragma unroll
                    for (int q = 0; q < vb.num_elements; q++) vb.x[q] = wmma::__float_to_tf32(vb.x[q]);
                    wmma::mma_sync(of, pa[kk], vb, of);
                }
                wmma::store_matrix_sync(sO + warp*16*FLD + j*16, of, FLD, wmma::mem_row_major);
            }
        }
    }
    __syncthreads();
    // normalize + write y[l, h*48+c]
    {
        float inv = 1.0f / sL[rr];
        const float* orow = sO + rr*FLD + hf*24;
        float* dst = g_y + (size_t)(l0+rr)*EE + hh*HDIM + hf*24;
#pragma unroll
        for (int c = 0; c < 24; c++) dst[c] = orow[c]*inv;
    }
}

// ---------------- driver ----------------
extern "C" void kernel_launch(void* const* d_in, const int* in_sizes, int n_in,
                              void* d_out, int out_size) {
    const float* z    = (const float*)d_in[0];
    const float* t    = (const float*)d_in[1];
    const float* bias = (const float*)d_in[2];
    const float* ln_g = (const float*)d_in[3];
    const float* ln_b = (const float*)d_in[4];
    const float* p2sw = (const float*)d_in[5];
    const float* t0w  = (const float*)d_in[6];
    const float* t0b  = (const float*)d_in[7];
    const float* t2w  = (const float*)d_in[8];
    const float* t2b  = (const float*)d_in[9];
    const float* pw   = (const float*)d_in[10];
    const float* ow   = (const float*)d_in[11];
    const float* ob   = (const float*)d_in[12];
    const float* aw   = (const float*)d_in[13];
    const float* ab   = (const float*)d_in[14];
    const float* f1w  = (const float*)d_in[15];
    const float* f1b  = (const float*)d_in[16];
    const float* f2w  = (const float*)d_in[17];
    const float* f2b  = (const float*)d_in[18];
    const float* faw  = (const float*)d_in[19];
    const float* fab  = (const float*)d_in[20];
    const float* fw   = (const float*)d_in[21];
    const float* fb   = (const float*)d_in[22];

    float *px, *ph, *pq, *py, *pm;
    cudaGetSymbolAddress((void**)&px, g_x);
    cudaGetSymbolAddress((void**)&ph, g_h);
    cudaGetSymbolAddress((void**)&pq, g_qkv);
    cudaGetSymbolAddress((void**)&py, g_y);
    cudaGetSymbolAddress((void**)&pm, g_mlp);

    k_copy<<<768, 1024>>>(z);
    k_prep<<<1, 128>>>(ln_g, ln_b, p2sw);
    k_bias<<<4096, 256>>>(bias);
    k_time1<<<1, 256>>>(t, t0w, t0b);
    k_time2<<<1, 256>>>(t2w, t2b);
    k_ada<<<4800, 256>>>(aw, ab, faw, fab);

    for (int d = 0; d < NDEPTH; d++) {
        const int base = d*6*EE;
        // attention branch
        k_lnmod<<<1024, 256>>>(px, base, base + EE, ph);
        k_gemm<0><<<dim3(36, 8), 256>>>(ph, pw + (size_t)d*3*EE*EE, nullptr, 0,
                                        pq, LL, 3*EE, EE);
        k_flash<<<dim3(16, 16), 128>>>();
        k_gemm<1><<<dim3(12, 8), 256>>>(py, ow + (size_t)d*EE*EE, ob + d*EE, base + 2*EE,
                                        px, LL, EE, EE);
        // MLP branch
        k_lnmod<<<1024, 256>>>(px, base + 3*EE, base + 4*EE, ph);
        k_gemm<2><<<dim3(48, 8), 256>>>(ph, f1w + (size_t)d*MLPD*EE, f1b + d*MLPD, 0,
                                        pm, LL, MLPD, EE);
        k_gemm<1><<<dim3(12, 8), 256>>>(pm, f2w + (size_t)d*EE*MLPD, f2b + d*EE, base + 5*EE,
                                        px, LL, EE, MLPD);
    }
    // final
    const int foff = NDEPTH*6*EE;
    k_lnmod<<<1024, 256>>>(px, foff, foff + EE, ph);
    k_gemm<0><<<dim3(12, 8), 256>>>(ph, fw, fb, 0, (float*)d_out, LL, EE, EE);
}

// round 8
// speedup vs baseline: 1.3146x; 1.3146x over previous
#include <cuda_runtime.h>
#include <cuda_bf16.h>
#include <mma.h>
#include <cmath>

using namespace nvcuda;

#define LL     1024
#define EE     768
#define PPD    128
#define HH     16
#define HDIM   48
#define NDEPTH 8
#define MLPD   3072
#define NFREQ  256

// ---------------- device-global scratch (no allocations allowed) ----------------
__device__ __align__(16) float g_x[LL*EE];
__device__ __align__(16) float g_h[LL*EE];
__device__ __align__(16) float g_qkv[LL*3*EE];
__device__ __align__(16) float g_y[LL*EE];
__device__ __align__(16) float g_mlp[LL*MLPD];
__device__ __align__(16) __nv_bfloat16 g_bh[(size_t)HH*LL*LL];   // 32 MB, [h][l][m]
__device__ float g_cpre[EE];
__device__ float g_cs[EE];
__device__ float g_ada[NDEPTH*6*EE + 2*EE];
__device__ float g_Apw[HH*PPD];
__device__ float g_Spw[HH];
__device__ float g_Cpw[HH];

// ---------------- init ----------------
__global__ void k_copy(const float* __restrict__ z) {
    int i = blockIdx.x*1024 + threadIdx.x;
    g_x[i] = z[i];
}

__global__ void k_prep(const float* __restrict__ g, const float* __restrict__ beta,
                       const float* __restrict__ w) {
    const int p = threadIdx.x; // 128
    for (int h = 0; h < HH; h++)
        g_Apw[h*PPD + p] = g[p] * w[h*PPD + p];
    if (p < HH) {
        float s = 0.f, c = 0.f;
        for (int q = 0; q < PPD; q++) {
            s += g[q]    * w[p*PPD + q];
            c += beta[q] * w[p*PPD + q];
        }
        g_Spw[p] = s; g_Cpw[p] = c;
    }
}

// ---------------- bias LN + head projection: 512 MB read, one thread per row ----------------
__global__ void __launch_bounds__(256) k_bias(const float* __restrict__ bias) {
    __shared__ __align__(16) float sA[HH*PPD];
    __shared__ float sSh[HH], sCh[HH];
    const int tid = threadIdx.x;
    for (int i = tid; i < HH*PPD; i += 256) sA[i] = g_Apw[i];
    if (tid < HH) { sSh[tid] = g_Spw[tid]; sCh[tid] = g_Cpw[tid]; }
    __syncthreads();
    const int row = blockIdx.x*256 + tid;      // row = l*1024 + m
    const float* xr = bias + (size_t)row*PPD;
    float acc[HH];
#pragma unroll
    for (int h = 0; h < HH; h++) acc[h] = 0.f;
    float s = 0.f, ss = 0.f;
#pragma unroll
    for (int ch = 0; ch < 4; ch++) {
        float4 xv[8];
#pragma unroll
        for (int j = 0; j < 8; j++) xv[j] = *(const float4*)&xr[ch*32 + j*4];
#pragma unroll
        for (int j = 0; j < 8; j++) {
            s  += xv[j].x + xv[j].y + xv[j].z + xv[j].w;
            ss += xv[j].x*xv[j].x + xv[j].y*xv[j].y + xv[j].z*xv[j].z + xv[j].w*xv[j].w;
        }
#pragma unroll
        for (int h = 0; h < HH; h++) {
            const float* ar = &sA[h*PPD + ch*32];
            float a0 = 0.f;
#pragma unroll
            for (int j = 0; j < 8; j++) {
                float4 av = *(const float4*)&ar[j*4];
                a0 += xv[j].x*av.x + xv[j].y*av.y + xv[j].z*av.z + xv[j].w*av.w;
            }
            acc[h] += a0;
        }
    }
    const float mu   = s * (1.0f/PPD);
    const float rstd = rsqrtf(ss*(1.0f/PPD) - mu*mu + 1e-6f);
    const int l = row >> 10, m = row & 1023;
#pragma unroll
    for (int h = 0; h < HH; h++) {
        float v = rstd*(acc[h] - mu*sSh[h]) + sCh[h];
        g_bh[((size_t)h << 20) + ((size_t)l << 10) + m] = __float2bfloat16(v);
    }
}

// ---------------- time embedding chain (parallel: one warp per output row) ----------------
__global__ void __launch_bounds__(256) k_time1(const float* __restrict__ t,
                                               const float* __restrict__ t0_w,
                                               const float* __restrict__ t0_b) {
    __shared__ float emb[NFREQ];
    const int tid = threadIdx.x;  // 256
    {
        int i = tid & 127;
        float f   = expf(-9.210340371976184f * (float)i / 128.0f);
        float arg = t[0] * f;
        emb[tid] = (tid < 128) ? cosf(arg) : sinf(arg);
    }
    __syncthreads();
    const int warp = tid >> 5, lane = tid & 31;
    const int j = blockIdx.x*8 + warp;          // grid 96 -> 768 rows
    const float* w = t0_w + (size_t)j*NFREQ;
    float acc = 0.f;
#pragma unroll
    for (int i = 0; i < 8; i++) acc += emb[lane + i*32] * w[lane + i*32];
#pragma unroll
    for (int o = 16; o > 0; o >>= 1) acc += __shfl_xor_sync(0xffffffffu, acc, o);
    if (lane == 0) {
        float a = acc + t0_b[j];
        g_cpre[j] = a / (1.f + expf(-a));
    }
}

__global__ void __launch_bounds__(256) k_time2(const float* __restrict__ t2_w,
                                               const float* __restrict__ t2_b) {
    __shared__ float cp[EE];
    const int tid = threadIdx.x;  // 256
    for (int i = tid; i < EE; i += 256) cp[i] = g_cpre[i];
    __syncthreads();
    const int warp = tid >> 5, lane = tid & 31;
    const int j = blockIdx.x*8 + warp;          // grid 96 -> 768 rows
    const float* w = t2_w + (size_t)j*EE;
    float acc = 0.f;
#pragma unroll
    for (int i = 0; i < 24; i++) acc += cp[lane + i*32] * w[lane + i*32];
#pragma unroll
    for (int o = 16; o > 0; o >>= 1) acc += __shfl_xor_sync(0xffffffffu, acc, o);
    if (lane == 0) {
        float a = acc + t2_b[j];
        g_cs[j] = a / (1.f + expf(-a));
    }
}

// all adaLN vectors (8*4608 + 1536 rows), one warp per row
__global__ void k_ada(const float* __restrict__ aw, const float* __restrict__ ab,
                      const float* __restrict__ fw, const float* __restrict__ fb) {
    const int gw   = (blockIdx.x*blockDim.x + threadIdx.x) >> 5;
    const int lane = threadIdx.x & 31;
    const int total = NDEPTH*6*EE + 2*EE;
    if (gw >= total) return;
    const float* wrow; float b;
    if (gw < NDEPTH*6*EE) { wrow = aw + (size_t)gw*EE; b = ab[gw]; }
    else { int r = gw - NDEPTH*6*EE; wrow = fw + (size_t)r*EE; b = fb[r]; }
    float acc = 0.f;
    for (int i = lane; i < EE; i += 32) acc += g_cs[i]*wrow[i];
#pragma unroll
    for (int o = 16; o > 0; o >>= 1) acc += __shfl_xor_sync(0xffffffffu, acc, o);
    if (lane == 0) g_ada[gw] = acc + b;
}

// ---------------- LayerNorm + adaLN modulation ----------------
__global__ void __launch_bounds__(256) k_lnmod(const float* __restrict__ x,
                                               int sh_off, int sc_off,
                                               float* __restrict__ out) {
    const int row = blockIdx.x, tid = threadIdx.x;
    const float* xr = x + (size_t)row*EE;
    float v0 = xr[tid], v1 = xr[tid+256], v2 = xr[tid+512];
    float s  = v0 + v1 + v2;
    float ss = v0*v0 + v1*v1 + v2*v2;
    __shared__ float rs[8], rss[8];
#pragma unroll
    for (int o = 16; o > 0; o >>= 1) {
        s  += __shfl_xor_sync(0xffffffffu, s,  o);
        ss += __shfl_xor_sync(0xffffffffu, ss, o);
    }
    if ((tid & 31) == 0) { rs[tid>>5] = s; rss[tid>>5] = ss; }
    __syncthreads();
    float st = 0.f, sst = 0.f;
#pragma unroll
    for (int i = 0; i < 8; i++) { st += rs[i]; sst += rss[i]; }
    const float mu   = st * (1.0f/EE);
    const float rstd = rsqrtf(sst*(1.0f/EE) - mu*mu + 1e-6f);
    const float* sh = g_ada + sh_off;
    const float* sc = g_ada + sc_off;
    float* orow = out + (size_t)row*EE;
    orow[tid]     = (v0-mu)*rstd*(1.f+sc[tid])     + sh[tid];
    orow[tid+256] = (v1-mu)*rstd*(1.f+sc[tid+256]) + sh[tid+256];
    orow[tid+512] = (v2-mu)*rstd*(1.f+sc[tid+512]) + sh[tid+512];
}

// ---------------- tf32 wmma GEMM: C(MxN) = A(MxK) @ W(NxK)^T, fused epilogue ----------------
// EPI 0: out = acc+bias    EPI 1: out += g_ada[g_off+n]*(acc+bias)    EPI 2: out = gelu_tanh(acc+bias)
// Templated tile BM x BN (warps of 32x32), float4 loads + register prefetch (single smem buffer).
#define GBK 32
#define GLD 36

template<int EPI, int BM, int BN>
__global__ void __launch_bounds__((BM/32)*(BN/32)*32) k_gemm(
        const float* __restrict__ A, const float* __restrict__ W,
        const float* __restrict__ bias, int g_off,
        float* __restrict__ out, int M, int N, int K) {
    constexpr int WM = BM/32, WN = BN/32;
    constexpr int NW = WM*WN;
    constexpr int T  = NW*32;
    constexpr int AF4 = BM*8/T;       // float4 per thread for A tile (BM x 32)
    constexpr int BF4 = BN*8/T;       // float4 per thread for B tile (BN x 32)
    constexpr int SMSZ = ((BM+BN)*GLD > NW*32*GLD) ? (BM+BN)*GLD : NW*32*GLD;

    __shared__ __align__(16) float smem[SMSZ];
    float* sA = smem;
    float* sB = smem + BM*GLD;
    const int tid = threadIdx.x;
    const int warp = tid >> 5, lane = tid & 31;
    const int wm = warp % WM, wn = warp / WM;
    const int m0 = blockIdx.y * BM;
    const int n0 = blockIdx.x * BN;

    wmma::fragment<wmma::accumulator,16,16,8,float> cf[2][2];
#pragma unroll
    for (int i = 0; i < 2; i++)
#pragma unroll
        for (int j = 0; j < 2; j++) wmma::fill_fragment(cf[i][j], 0.0f);

    float4 ra[AF4], rb[BF4];
    // prefetch k0 = 0
#pragma unroll
    for (int i = 0; i < AF4; i++) {
        int f = tid + i*T;
        ra[i] = *(const float4*)&A[(size_t)(m0 + (f>>3))*K + ((f&7)<<2)];
    }
#pragma unroll
    for (int i = 0; i < BF4; i++) {
        int f = tid + i*T;
        rb[i] = *(const float4*)&W[(size_t)(n0 + (f>>3))*K + ((f&7)<<2)];
    }

    for (int k0 = 0; k0 < K; k0 += GBK) {
        // store current regs into smem
#pragma unroll
        for (int i = 0; i < AF4; i++) {
            int f = tid + i*T;
            *(float4*)&sA[(f>>3)*GLD + ((f&7)<<2)] = ra[i];
        }
#pragma unroll
        for (int i = 0; i < BF4; i++) {
            int f = tid + i*T;
            *(float4*)&sB[(f>>3)*GLD + ((f&7)<<2)] = rb[i];
        }
        __syncthreads();
        // prefetch next chunk (overlaps with mma work)
        if (k0 + GBK < K) {
            const int kn = k0 + GBK;
#pragma unroll
            for (int i = 0; i < AF4; i++) {
                int f = tid + i*T;
                ra[i] = *(const float4*)&A[(size_t)(m0 + (f>>3))*K + kn + ((f&7)<<2)];
            }
#pragma unroll
            for (int i = 0; i < BF4; i++) {
                int f = tid + i*T;
                rb[i] = *(const float4*)&W[(size_t)(n0 + (f>>3))*K + kn + ((f&7)<<2)];
            }
        }
#pragma unroll
        for (int kk = 0; kk < 4; kk++) {
            wmma::fragment<wmma::matrix_a,16,16,8,wmma::precision::tf32,wmma::row_major> af[2];
            wmma::fragment<wmma::matrix_b,16,16,8,wmma::precision::tf32,wmma::col_major> bf[2];
#pragma unroll
            for (int i = 0; i < 2; i++) {
                wmma::load_matrix_sync(af[i], sA + (wm*32 + i*16)*GLD + kk*8, GLD);
#pragma unroll
                for (int q = 0; q < af[i].num_elements; q++) af[i].x[q] = wmma::__float_to_tf32(af[i].x[q]);
            }
#pragma unroll
            for (int j = 0; j < 2; j++) {
                wmma::load_matrix_sync(bf[j], sB + (wn*32 + j*16)*GLD + kk*8, GLD);
#pragma unroll
                for (int q = 0; q < bf[j].num_elements; q++) bf[j].x[q] = wmma::__float_to_tf32(bf[j].x[q]);
            }
#pragma unroll
            for (int i = 0; i < 2; i++)
#pragma unroll
                for (int j = 0; j < 2; j++) wmma::mma_sync(cf[i][j], af[i], bf[j], cf[i][j]);
        }
        __syncthreads();
    }
    float* cbuf = smem + warp*(32*GLD);
#pragma unroll
    for (int i = 0; i < 2; i++)
#pragma unroll
        for (int j = 0; j < 2; j++)
            wmma::store_matrix_sync(cbuf + (i*16)*GLD + j*16, cf[i][j], GLD, wmma::mem_row_major);
    __syncwarp();
    const int ncol = n0 + wn*32 + lane;
    const float bv = bias ? bias[ncol] : 0.0f;
    const float gv = (EPI == 1) ? g_ada[g_off + ncol] : 0.0f;
#pragma unroll 8
    for (int r = 0; r < 32; r++) {
        float v = cbuf[r*GLD + lane] + bv;
        size_t oi = (size_t)(m0 + wm*32 + r)*N + ncol;
        if (EPI == 0) {
            out[oi] = v;
        } else if (EPI == 1) {
            out[oi] = out[oi] + gv * v;
        } else {
            float tn = tanhf(0.7978845608028654f*(v + 0.044715f*v*v*v));
            out[oi] = 0.5f*v*(1.0f + tn);
        }
    }
}

// ---------------- fused flash attention: one CTA per (q-tile 64, head) ----------------
#define FLD  48
#define FLDS 36

__global__ void __launch_bounds__(128) k_flash() {
    __shared__ __align__(16) float fs[11648];
    float* sQ = fs;                // 64 x 48
    float* sK = fs + 3072;         // 32 x 48
    float* sV = fs + 4608;         // 32 x 48
    float* sO = fs + 6144;         // 64 x 48
    float* sS = fs + 9216;         // 64 x 36 (32 cols used)
    float* sM = fs + 11520;        // 64
    float* sL = fs + 11584;        // 64

    const int tid  = threadIdx.x;  // 128
    const int warp = tid >> 5;
    const int qt = blockIdx.x, hh = blockIdx.y;
    const int l0 = qt*64;
    const float scale = 0.14433756729740643f;   // 48^-0.5
    const int rr = tid >> 1, hf = tid & 1;

    // load scaled Q tile (64 x 48)
#pragma unroll
    for (int i = 0; i < 6; i++) {
        int e = tid + i*128;
        int r = e/12, c4 = e%12;
        float4 v = *(const float4*)&g_qkv[(size_t)(l0+r)*(3*EE) + hh*144 + c4*4];
        v.x *= scale; v.y *= scale; v.z *= scale; v.w *= scale;
        *(float4*)&sQ[r*FLD + c4*4] = v;
    }
    for (int i = tid; i < 64*FLD; i += 128) sO[i] = 0.0f;
    if (tid < 64) { sM[tid] = -1e30f; sL[tid] = 0.0f; }

    // register prefetch of K/V tile 0
    const int pr = tid/12, pc4 = tid%12;        // covers 3 rows-chunks below
    float4 pk[3], pv[3];
#pragma unroll
    for (int i = 0; i < 3; i++) {
        int e = tid + i*128;
        int r = e/12, c4 = e%12;
        pk[i] = *(const float4*)&g_qkv[(size_t)r*(3*EE) + hh*144 + 48 + c4*4];
        pv[i] = *(const float4*)&g_qkv[(size_t)r*(3*EE) + hh*144 + 96 + c4*4];
    }
    (void)pr; (void)pc4;

    for (int mt = 0; mt < 32; mt++) {
        const int m0 = mt*32;
        __syncthreads();                       // protects sK/sV reuse (+ init on iter 0)
#pragma unroll
        for (int i = 0; i < 3; i++) {
            int e = tid + i*128;
            int r = e/12, c4 = e%12;
            *(float4*)&sK[r*FLD + c4*4] = pk[i];
            *(float4*)&sV[r*FLD + c4*4] = pv[i];
        }
        __syncthreads();
        // prefetch next tile (overlaps with S/softmax/PV)
        if (mt < 31) {
            const int mn = m0 + 32;
#pragma unroll
            for (int i = 0; i < 3; i++) {
                int e = tid + i*128;
                int r = e/12, c4 = e%12;
                pk[i] = *(const float4*)&g_qkv[(size_t)(mn+r)*(3*EE) + hh*144 + 48 + c4*4];
                pv[i] = *(const float4*)&g_qkv[(size_t)(mn+r)*(3*EE) + hh*144 + 96 + c4*4];
            }
        }
        // S = Q @ K^T : warp handles rows warp*16..+15, cols 0..31
#pragma unroll
        for (int nt = 0; nt < 2; nt++) {
            wmma::fragment<wmma::accumulator,16,16,8,float> sc;
            wmma::fill_fragment(sc, 0.0f);
#pragma unroll
            for (int k = 0; k < 6; k++) {
                wmma::fragment<wmma::matrix_a,16,16,8,wmma::precision::tf32,wmma::row_major> af;
                wmma::fragment<wmma::matrix_b,16,16,8,wmma::precision::tf32,wmma::col_major> bf;
                wmma::load_matrix_sync(af, sQ + warp*16*FLD + k*8, FLD);
                wmma::load_matrix_sync(bf, sK + nt*16*FLD + k*8, FLD);
#pragma unroll
                for (int q = 0; q < af.num_elements; q++) af.x[q] = wmma::__float_to_tf32(af.x[q]);
#pragma unroll
                for (int q = 0; q < bf.num_elements; q++) bf.x[q] = wmma::__float_to_tf32(bf.x[q]);
                wmma::mma_sync(sc, af, bf, sc);
            }
            wmma::store_matrix_sync(sS + warp*16*FLDS + nt*16, sc, FLDS, wmma::mem_row_major);
        }
        __syncthreads();
        // bias add + online softmax: 2 threads per row, 16 cols each
        {
            const int c0 = hf*16;
            const __nv_bfloat16* bp = &g_bh[((size_t)hh << 20) + ((size_t)(l0+rr) << 10) + m0 + c0];
            float* srow = sS + rr*FLDS + c0;
            float v[16];
            float mloc = -1e30f;
#pragma unroll
            for (int c = 0; c < 16; c++) {
                v[c] = srow[c] + __bfloat162float(bp[c]);
                mloc = fmaxf(mloc, v[c]);
            }
            mloc = fmaxf(mloc, __shfl_xor_sync(0xffffffffu, mloc, 1));
            float mprev = sM[rr];
            float mnew  = fmaxf(mprev, mloc);
            float sum = 0.f;
#pragma unroll
            for (int c = 0; c < 16; c++) {
                float p = __expf(v[c] - mnew);
                srow[c] = p;
                sum += p;
            }
            sum += __shfl_xor_sync(0xffffffffu, sum, 1);
            float factor = __expf(mprev - mnew);
            if (hf == 0) { sM[rr] = mnew; sL[rr] = sL[rr]*factor + sum; }
            float* orow = sO + rr*FLD + hf*24;
#pragma unroll
            for (int c = 0; c < 24; c++) orow[c] *= factor;
        }
        __syncthreads();
        // O += P(64x32) @ V(32x48) : warp handles its 16 rows, 3 col tiles
        {
            wmma::fragment<wmma::matrix_a,16,16,8,wmma::precision::tf32,wmma::row_major> pa[4];
#pragma unroll
            for (int kk = 0; kk < 4; kk++) {
                wmma::load_matrix_sync(pa[kk], sS + warp*16*FLDS + kk*8, FLDS);
#pragma unroll
                for (int q = 0; q < pa[kk].num_elements; q++) pa[kk].x[q] = wmma::__float_to_tf32(pa[kk].x[q]);
            }
#pragma unroll
            for (int j = 0; j < 3; j++) {
                wmma::fragment<wmma::accumulator,16,16,8,float> of;
                wmma::load_matrix_sync(of, sO + warp*16*FLD + j*16, FLD, wmma::mem_row_major);
#pragma unroll
                for (int kk = 0; kk < 4; kk++) {
                    wmma::fragment<wmma::matrix_b,16,16,8,wmma::precision::tf32,wmma::row_major> vb;
                    wmma::load_matrix_sync(vb, sV + kk*8*FLD + j*16, FLD);
#pragma unroll
                    for (int q = 0; q < vb.num_elements; q++) vb.x[q] = wmma::__float_to_tf32(vb.x[q]);
                    wmma::mma_sync(of, pa[kk], vb, of);
                }
                wmma::store_matrix_sync(sO + warp*16*FLD + j*16, of, FLD, wmma::mem_row_major);
            }
        }
    }
    __syncthreads();
    // normalize + write y[l, h*48+c]
    {
        float inv = 1.0f / sL[rr];
        const float* orow = sO + rr*FLD + hf*24;
        float* dst = g_y + (size_t)(l0+rr)*EE + hh*HDIM + hf*24;
#pragma unroll
        for (int c = 0; c < 24; c++) dst[c] = orow[c]*inv;
    }
}

// ---------------- driver ----------------
extern "C" void kernel_launch(void* const* d_in, const int* in_sizes, int n_in,
                              void* d_out, int out_size) {
    const float* z    = (const float*)d_in[0];
    const float* t    = (const float*)d_in[1];
    const float* bias = (const float*)d_in[2];
    const float* ln_g = (const float*)d_in[3];
    const float* ln_b = (const float*)d_in[4];
    const float* p2sw = (const float*)d_in[5];
    const float* t0w  = (const float*)d_in[6];
    const float* t0b  = (const float*)d_in[7];
    const float* t2w  = (const float*)d_in[8];
    const float* t2b  = (const float*)d_in[9];
    const float* pw   = (const float*)d_in[10];
    const float* ow   = (const float*)d_in[11];
    const float* ob   = (const float*)d_in[12];
    const float* aw   = (const float*)d_in[13];
    const float* ab   = (const float*)d_in[14];
    const float* f1w  = (const float*)d_in[15];
    const float* f1b  = (const float*)d_in[16];
    const float* f2w  = (const float*)d_in[17];
    const float* f2b  = (const float*)d_in[18];
    const float* faw  = (const float*)d_in[19];
    const float* fab  = (const float*)d_in[20];
    const float* fw   = (const float*)d_in[21];
    const float* fb   = (const float*)d_in[22];

    float *px, *ph, *pq, *py, *pm;
    cudaGetSymbolAddress((void**)&px, g_x);
    cudaGetSymbolAddress((void**)&ph, g_h);
    cudaGetSymbolAddress((void**)&pq, g_qkv);
    cudaGetSymbolAddress((void**)&py, g_y);
    cudaGetSymbolAddress((void**)&pm, g_mlp);

    k_copy<<<768, 1024>>>(z);
    k_prep<<<1, 128>>>(ln_g, ln_b, p2sw);
    k_bias<<<4096, 256>>>(bias);
    k_time1<<<96, 256>>>(t, t0w, t0b);
    k_time2<<<96, 256>>>(t2w, t2b);
    k_ada<<<4800, 256>>>(aw, ab, faw, fab);

    for (int d = 0; d < NDEPTH; d++) {
        const int base = d*6*EE;
        // attention branch
        k_lnmod<<<1024, 256>>>(px, base, base + EE, ph);
        k_gemm<0,128,64><<<dim3(36, 8), 256>>>(ph, pw + (size_t)d*3*EE*EE, nullptr, 0,
                                               pq, LL, 3*EE, EE);
        k_flash<<<dim3(16, 16), 128>>>();
        k_gemm<1,64,64><<<dim3(12, 16), 128>>>(py, ow + (size_t)d*EE*EE, ob + d*EE, base + 2*EE,
                                               px, LL, EE, EE);
        // MLP branch
        k_lnmod<<<1024, 256>>>(px, base + 3*EE, base + 4*EE, ph);
        k_gemm<2,128,64><<<dim3(48, 8), 256>>>(ph, f1w + (size_t)d*MLPD*EE, f1b + d*MLPD, 0,
                                               pm, LL, MLPD, EE);
        k_gemm<1,64,64><<<dim3(12, 16), 128>>>(pm, f2w + (size_t)d*EE*MLPD, f2b + d*EE, base + 5*EE,
                                               px, LL, EE, MLPD);
    }
    // final
    const int foff = NDEPTH*6*EE;
    k_lnmod<<<1024, 256>>>(px, foff, foff + EE, ph);
    k_gemm<0,64,64><<<dim3(12, 16), 128>>>(ph, fw, fb, 0, (float*)d_out, LL, EE, EE);
}